// round 1
// baseline (speedup 1.0000x reference)
#include <cuda_runtime.h>

#define BB 4
#define NT 256
#define NZ 384
#define NXX 384
#define NREC 128
#define DT 0.001f
#define DH 10.0f
#define NPTS (BB * NZ * NXX)

// Ping-pong wavefields. step t: h1 = d_h[t&1], h2 = d_h[(t&1)^1]; hn overwrites h2's buffer.
__device__ float d_h[2][NPTS];

__global__ void zero_kernel() {
    int i = blockIdx.x * blockDim.x + threadIdx.x;
    if (i < NPTS) {
        d_h[0][i] = 0.0f;
        d_h[1][i] = 0.0f;
    }
}

__global__ __launch_bounds__(256) void step_kernel(
    const float* __restrict__ xsrc,   // [B, NT]
    const float* __restrict__ vp,     // [NZ, NX]
    const int*   __restrict__ src_y,  // [B]
    const int*   __restrict__ src_x,  // [B]
    const int*   __restrict__ rec_y,  // [NREC]
    const int*   __restrict__ rec_x,  // [NREC]
    float*       __restrict__ out,    // [NT, B, NREC]
    int t)
{
    const float inv_dh2 = 1.0f / (DH * DH);
    const int gid = blockIdx.x * blockDim.x + threadIdx.x;

    const float* __restrict__ h1 = d_h[t & 1];
    float*       __restrict__ h2 = d_h[(t & 1) ^ 1];

    // Gather receivers for step t-1 (h1 == hn(t-1), fully written by previous launch).
    if (t > 0 && gid < BB * NREC) {
        const int b = gid / NREC;
        const int r = gid % NREC;
        out[(t - 1) * (BB * NREC) + gid] =
            h1[b * NZ * NXX + rec_y[r] * NXX + rec_x[r]];
    }

    if (gid >= NPTS) return;

    const int xx = gid % NXX;
    const int z  = (gid / NXX) % NZ;
    const int b  = gid / (NZ * NXX);

    const float u = h1[gid];
    float lap = 0.0f;
    if (z > 0 && z < NZ - 1 && xx > 0 && xx < NXX - 1) {
        lap = (h1[gid - NXX] + h1[gid + NXX] + h1[gid - 1] + h1[gid + 1]
               - 4.0f * u) * inv_dh2;
    }
    const float c  = vp[z * NXX + xx] * DT;
    float hn = 2.0f * u - h2[gid] + (c * c) * lap;

    if (z == src_y[b] && xx == src_x[b]) {
        hn += xsrc[b * NT + t];
    }
    h2[gid] = hn;   // in-place: new hn replaces old h2 (only this thread touches h2[gid])
}

__global__ void final_gather(const int* __restrict__ rec_y,
                             const int* __restrict__ rec_x,
                             float* __restrict__ out)
{
    int gid = blockIdx.x * blockDim.x + threadIdx.x;
    if (gid < BB * NREC) {
        const int b = gid / NREC;
        const int r = gid % NREC;
        // Step NT-1 (t=255, odd) wrote its hn into d_h[0] == d_h[NT & 1].
        out[(NT - 1) * (BB * NREC) + gid] =
            d_h[NT & 1][b * NZ * NXX + rec_y[r] * NXX + rec_x[r]];
    }
}

extern "C" void kernel_launch(void* const* d_in, const int* in_sizes, int n_in,
                              void* d_out, int out_size)
{
    const float* xsrc  = (const float*)d_in[0];  // [B, NT]
    const float* vp    = (const float*)d_in[1];  // [NZ, NX]
    const int*   src_y = (const int*)d_in[2];    // [B]
    const int*   src_x = (const int*)d_in[3];    // [B]
    const int*   rec_y = (const int*)d_in[4];    // [NREC]
    const int*   rec_x = (const int*)d_in[5];    // [NREC]
    float*       out   = (float*)d_out;          // [NT, B, NREC]

    const int threads = 256;
    const int zblocks = (NPTS + threads - 1) / threads;

    zero_kernel<<<zblocks, threads>>>();

    for (int t = 0; t < NT; t++) {
        step_kernel<<<zblocks, threads>>>(xsrc, vp, src_y, src_x,
                                          rec_y, rec_x, out, t);
    }

    final_gather<<<(BB * NREC + threads - 1) / threads, threads>>>(rec_y, rec_x, out);
}

// round 2
// speedup vs baseline: 1.1197x; 1.1197x over previous
#include <cuda_runtime.h>

#define BB 4
#define NT 256
#define NZ 384
#define NXX 384
#define NREC 128
#define DTc 0.001f
#define DHc 10.0f

#define NBLK 128
#define BLK_PER_B (NBLK / BB)      // 32 blocks per batch
#define ROWS (NZ / BLK_PER_B)      // 12 rows per block
#define NTHR 512
#define PTS (ROWS * NXX)           // 4608 points per block
#define PPT (PTS / NTHR)           // 9 points per thread

// Neighbor-sync state (reset by zero_kernel each call; fields live in smem/regs only).
__device__ int   d_flags[NBLK];                 // steps completed per block
__device__ float d_halo[2][NBLK][2][NXX];       // [slot][block][top/bot row][x]

__global__ void zero_kernel() {
    int i = blockIdx.x * blockDim.x + threadIdx.x;
    if (i < NBLK) d_flags[i] = 0;
    const int n = 2 * NBLK * 2 * NXX;
    for (int j = i; j < n; j += gridDim.x * blockDim.x)
        ((float*)d_halo)[j] = 0.0f;
}

__global__ __launch_bounds__(NTHR) void wave_kernel(
    const float* __restrict__ xsrc,   // [B, NT]
    const float* __restrict__ vp,     // [NZ, NX]
    const int*   __restrict__ src_y,  // [B]
    const int*   __restrict__ src_x,  // [B]
    const int*   __restrict__ rec_y,  // [NREC]
    const int*   __restrict__ rec_x,  // [NREC]
    float*       __restrict__ out)    // [NT, B, NREC]
{
    __shared__ float sbuf[2][ROWS * NXX];   // double-buffered field tile

    const int tid = threadIdx.x;
    const int blk = blockIdx.x;
    const int b   = blk / BLK_PER_B;
    const int bib = blk % BLK_PER_B;
    const int z0  = bib * ROWS;             // domain z of local row 0
    const float inv_dh2 = 1.0f / (DHc * DHc);

    const int topBlk = (bib > 0) ? blk - 1 : -1;
    const int botBlk = (bib < BLK_PER_B - 1) ? blk + 1 : -1;

    // ---- per-point init: registers + smem zero ----
    float ucur[PPT];   // field(t-1) at my points
    float uprev[PPT];  // field(t-2) at my points
    float c2[PPT];     // (vp*DT)^2
    int   smask = 0;   // source-injection bit per point

    const int sy = src_y[b];
    const int sx = src_x[b];

#pragma unroll
    for (int k = 0; k < PPT; k++) {
        const int p   = tid + k * NTHR;
        const int row = p / NXX;
        const int col = p % NXX;
        const int zg  = z0 + row;
        ucur[k]  = 0.0f;
        uprev[k] = 0.0f;
        const float c = vp[zg * NXX + col] * DTc;
        c2[k] = c * c;
        if (zg == sy && col == sx) smask |= (1 << k);
        sbuf[0][p] = 0.0f;
        sbuf[1][p] = 0.0f;
    }

    // receiver registers (thread tid handles receiver tid)
    int   rmine = 0, roff = 0, obase = 0;
    if (tid < NREC) {
        const int ry = rec_y[tid];
        const int rx = rec_x[tid];
        rmine = (ry >= z0 && ry < z0 + ROWS);
        roff  = (ry - z0) * NXX + rx;
        obase = b * NREC + tid;
    }
    const float* xs = xsrc + b * NT;

    __syncthreads();

    // ---- time loop ----
    for (int t = 0; t < NT; t++) {
        const int rd  = t & 1;        // smem buffer holding field(t-1)
        const int wr  = rd ^ 1;       // smem buffer to receive field(t)
        const int hrd = wr;           // halo slot holding neighbors' field(t-1) rows
        const int hwr = rd;           // halo slot for my field(t) rows

        // Phase 1: interior rows (1..ROWS-2) — no halo dependency.
#pragma unroll
        for (int k = 0; k < PPT; k++) {
            const int p   = tid + k * NTHR;
            const int row = p / NXX;
            if (row == 0 || row == ROWS - 1) continue;
            const int col = p % NXX;
            float lap = 0.0f;
            if (col > 0 && col < NXX - 1) {
                lap = (sbuf[rd][p - NXX] + sbuf[rd][p + NXX] +
                       sbuf[rd][p - 1]  + sbuf[rd][p + 1]  -
                       4.0f * ucur[k]) * inv_dh2;
            }
            float hn = 2.0f * ucur[k] - uprev[k] + c2[k] * lap;
            if (smask & (1 << k)) hn += xs[t];
            uprev[k] = ucur[k];
            ucur[k]  = hn;
            sbuf[wr][p] = hn;
        }

        // Wait for neighbors to have published field(t-1) boundary rows.
        if (tid == 0) {
            if (topBlk >= 0) {
                while (*((volatile int*)&d_flags[topBlk]) < t) { }
            }
            if (botBlk >= 0) {
                while (*((volatile int*)&d_flags[botBlk]) < t) { }
            }
            __threadfence();
        }
        __syncthreads();

        // Phase 2: boundary rows (0 and ROWS-1), using neighbor halo from L2.
#pragma unroll
        for (int k = 0; k < PPT; k++) {
            const int p   = tid + k * NTHR;
            const int row = p / NXX;
            if (row != 0 && row != ROWS - 1) continue;
            const int col = p % NXX;
            const int zg  = z0 + row;
            float hn;
            if (zg == 0 || zg == NZ - 1) {
                hn = 2.0f * ucur[k] - uprev[k];          // lap padded to 0
            } else {
                float lap = 0.0f;
                if (col > 0 && col < NXX - 1) {
                    const float up = (row == 0)
                        ? __ldcg(&d_halo[hrd][topBlk][1][col])
                        : sbuf[rd][p - NXX];
                    const float dn = (row == ROWS - 1)
                        ? __ldcg(&d_halo[hrd][botBlk][0][col])
                        : sbuf[rd][p + NXX];
                    lap = (up + dn + sbuf[rd][p - 1] + sbuf[rd][p + 1] -
                           4.0f * ucur[k]) * inv_dh2;
                }
                hn = 2.0f * ucur[k] - uprev[k] + c2[k] * lap;
            }
            if (smask & (1 << k)) hn += xs[t];
            uprev[k] = ucur[k];
            ucur[k]  = hn;
            sbuf[wr][p] = hn;
            // publish my field(t) boundary rows
            d_halo[hwr][blk][(row == 0) ? 0 : 1][col] = hn;
        }

        __syncthreads();   // field(t) complete in sbuf[wr]; halo stores issued

        if (tid == 0) {
            __threadfence();                          // halo rows visible first
            *((volatile int*)&d_flags[blk]) = t + 1;  // post completion
        }
        // receiver gather for step t (reads new buffer; overlaps with flag post)
        if (tid < NREC && rmine) {
            out[t * (BB * NREC) + obase] = sbuf[wr][roff];
        }
    }
}

extern "C" void kernel_launch(void* const* d_in, const int* in_sizes, int n_in,
                              void* d_out, int out_size)
{
    const float* xsrc  = (const float*)d_in[0];
    const float* vp    = (const float*)d_in[1];
    const int*   src_y = (const int*)d_in[2];
    const int*   src_x = (const int*)d_in[3];
    const int*   rec_y = (const int*)d_in[4];
    const int*   rec_x = (const int*)d_in[5];
    float*       out   = (float*)d_out;

    zero_kernel<<<128, 512>>>();
    wave_kernel<<<NBLK, NTHR>>>(xsrc, vp, src_y, src_x, rec_y, rec_x, out);
}